// round 1
// baseline (speedup 1.0000x reference)
#include <cuda_runtime.h>
#include <cstdint>

#define R        128
#define R2       (R * R)
#define R3       (R * R * R)
#define BATCH    2
#define NV_TOT   7700
#define NSURF_N  6890
#define NT_TOT   30000
#define EPS_W    0.001f
// 1/(2*sigma^2) with sigma = 0.05  -> 200
#define INV2SIG2 200.0f

// Scratch: per-voxel occupancy (0/1) and gaussian weight sum.
__device__ unsigned char g_occ[BATCH * R3];
__device__ float         g_wsum[BATCH * R3];

// ---------------------------------------------------------------------------
// init: occ = 0, wsum = EPS_W, out = 0 (out is poisoned by harness)
// ---------------------------------------------------------------------------
__global__ void init_kernel(float* __restrict__ out) {
    int i = blockIdx.x * blockDim.x + threadIdx.x;
    if (i >= BATCH * R3) return;
    g_occ[i]  = 0;
    g_wsum[i] = EPS_W;
    int b   = i >> 21;          // / R3  (R3 = 2^21)
    int vox = i & (R3 - 1);
    float* o = out + (size_t)b * 3 * R3 + vox;
    o[0]        = 0.0f;
    o[R3]       = 0.0f;
    o[2 * R3]   = 0.0f;
}

// ---------------------------------------------------------------------------
// tet occupancy: one block per (b, tet); 125 lanes cover the 5^3 window.
// ---------------------------------------------------------------------------
__global__ void tet_kernel(const float* __restrict__ verts,
                           const int*   __restrict__ tets) {
    int blk = blockIdx.x;           // b * NT + t
    int b = blk / NT_TOT;
    int t = blk - b * NT_TOT;
    int j = threadIdx.x;
    if (j >= 125) return;

    const int* ti = tets + (size_t)t * 4;
    const float* vb = verts + (size_t)b * NV_TOT * 3;

    const float* p0 = vb + (size_t)ti[0] * 3;
    const float* p1 = vb + (size_t)ti[1] * 3;
    const float* p2 = vb + (size_t)ti[2] * 3;
    const float* p3 = vb + (size_t)ti[3] * 3;

    float ax = p0[0], ay = p0[1], az = p0[2];
    float bxv = p1[0], byv = p1[1], bzv = p1[2];
    float cxv = p2[0], cyv = p2[1], czv = p2[2];
    float dxv = p3[0], dyv = p3[1], dzv = p3[2];

    float e1x = bxv - ax, e1y = byv - ay, e1z = bzv - az;
    float e2x = cxv - ax, e2y = cyv - ay, e2z = czv - az;
    float e3x = dxv - ax, e3y = dyv - ay, e3z = dzv - az;

    // c23 = cross(e2, e3)
    float c23x = e2y * e3z - e2z * e3y;
    float c23y = e2z * e3x - e2x * e3z;
    float c23z = e2x * e3y - e2y * e3x;

    float vol6 = e1x * c23x + e1y * c23y + e1z * c23z;
    bool volok = fabsf(vol6) > 1e-12f;
    float iv = volok ? (1.0f / vol6) : 1.0f;

    // anchor = floor(min over the 4 verts per coord * R)
    int anx = (int)floorf(fminf(fminf(ax, bxv), fminf(cxv, dxv)) * (float)R);
    int any_ = (int)floorf(fminf(fminf(ay, byv), fminf(cyv, dyv)) * (float)R);
    int anz = (int)floorf(fminf(fminf(az, bzv), fminf(czv, dzv)) * (float)R);

    // toff components: comp0 = j/25, comp1 = (j/5)%5, comp2 = j%5
    int t0 = anx + j / 25;
    int t1 = any_ + (j / 5) % 5;
    int t2 = anz + j % 5;

    if (t0 < 0 || t0 >= R || t1 < 0 || t1 >= R || t2 < 0 || t2 >= R) return;
    if (!volok) return;

    float px = ((float)t0 + 0.5f) * (1.0f / (float)R) - ax;
    float py = ((float)t1 + 0.5f) * (1.0f / (float)R) - ay;
    float pz = ((float)t2 + 0.5f) * (1.0f / (float)R) - az;

    float l1 = (px * c23x + py * c23y + pz * c23z) * iv;

    // cross(p, e3) . e1
    float q1x = py * e3z - pz * e3y;
    float q1y = pz * e3x - px * e3z;
    float q1z = px * e3y - py * e3x;
    float l2 = (q1x * e1x + q1y * e1y + q1z * e1z) * iv;

    // cross(e2, p) . e1
    float q2x = e2y * pz - e2z * py;
    float q2y = e2z * px - e2x * pz;
    float q2z = e2x * py - e2y * px;
    float l3 = (q2x * e1x + q2y * e1y + q2z * e1z) * iv;

    if (l1 >= 0.0f && l2 >= 0.0f && l3 >= 0.0f && (l1 + l2 + l3) <= 1.0f) {
        // linear: ((b*R + t2)*R + t1)*R + t0
        g_occ[b * R3 + (t2 * R + t1) * R + t0] = 1;
    }
}

// ---------------------------------------------------------------------------
// surface splat: one block per (b, surf vertex); 343 lanes cover 7^3 window.
// Accumulates wsum (device scratch) and the 3 semantic channels directly
// into d_out in planar (b, c, z, y, x) layout.
// ---------------------------------------------------------------------------
__global__ void splat_kernel(const float* __restrict__ verts,
                             const float* __restrict__ code,
                             float* __restrict__ out) {
    int blk = blockIdx.x;           // b * NSURF + v
    int b = blk / NSURF_N;
    int v = blk - b * NSURF_N;
    int j = threadIdx.x;
    if (j >= 343) return;

    const float* vp = verts + ((size_t)b * NV_TOT + v) * 3;
    float vx = vp[0], vy = vp[1], vz = vp[2];
    const float* cp = code + ((size_t)b * NSURF_N + v) * 3;
    float c0 = cp[0], c1 = cp[1], c2 = cp[2];

    int bx = (int)floorf(vx * (float)R);
    int by = (int)floorf(vy * (float)R);
    int bz = (int)floorf(vz * (float)R);

    // offs components: comp0 = j/49 - 3, comp1 = (j/7)%7 - 3, comp2 = j%7 - 3
    int s0 = bx + j / 49 - 3;
    int s1 = by + (j / 7) % 7 - 3;
    int s2 = bz + j % 7 - 3;
    if (s0 < 0 || s0 >= R || s1 < 0 || s1 >= R || s2 < 0 || s2 >= R) return;

    float dx = ((float)s0 + 0.5f) * (1.0f / (float)R) - vx;
    float dy = ((float)s1 + 0.5f) * (1.0f / (float)R) - vy;
    float dz = ((float)s2 + 0.5f) * (1.0f / (float)R) - vz;
    float d2 = dx * dx + dy * dy + dz * dz;
    float w = expf(-d2 * INV2SIG2);

    int vox = (s2 * R + s1) * R + s0;
    atomicAdd(&g_wsum[b * R3 + vox], w);

    size_t ob = (size_t)b * 3 * R3 + vox;
    atomicAdd(&out[ob],          w * c0);
    atomicAdd(&out[ob + R3],     w * c1);
    atomicAdd(&out[ob + 2 * R3], w * c2);
}

// ---------------------------------------------------------------------------
// finalize: out[c] = out[c] / wsum * occ  (planar layout already correct)
// ---------------------------------------------------------------------------
__global__ void finalize_kernel(float* __restrict__ out) {
    int i = blockIdx.x * blockDim.x + threadIdx.x;
    if (i >= BATCH * R3) return;
    int b   = i >> 21;
    int vox = i & (R3 - 1);
    float s = (float)g_occ[i] / g_wsum[i];
    size_t ob = (size_t)b * 3 * R3 + vox;
    out[ob]          *= s;
    out[ob + R3]     *= s;
    out[ob + 2 * R3] *= s;
}

// ---------------------------------------------------------------------------
extern "C" void kernel_launch(void* const* d_in, const int* in_sizes, int n_in,
                              void* d_out, int out_size) {
    const float* smpl_vertices = (const float*)d_in[0]; // (2, 7700, 3)
    const float* vertex_code   = (const float*)d_in[1]; // (2, 6890, 3)
    // d_in[2] = face_indices — dead code in the reference, unused.
    const int*   tet_indices   = (const int*)d_in[3];   // (30000, 4)
    float* out = (float*)d_out;                         // (2, 3, 128, 128, 128)

    {
        int n = BATCH * R3;
        init_kernel<<<(n + 255) / 256, 256>>>(out);
    }
    tet_kernel<<<BATCH * NT_TOT, 128>>>(smpl_vertices, tet_indices);
    splat_kernel<<<BATCH * NSURF_N, 352>>>(smpl_vertices, vertex_code, out);
    {
        int n = BATCH * R3;
        finalize_kernel<<<(n + 255) / 256, 256>>>(out);
    }
}

// round 2
// speedup vs baseline: 1.4880x; 1.4880x over previous
#include <cuda_runtime.h>
#include <cstdint>

#define R        128
#define R3       (R * R * R)
#define BATCH    2
#define NV_TOT   7700
#define NSURF_N  6890
#define NT_TOT   30000
#define EPS_W    0.001f
#define INV2SIG2 200.0f   // 1/(2*0.05^2)

// Scratch: per-voxel occupancy byte and interleaved accumulator
// acc = (sem0, sem1, sem2, wsum)
__device__ unsigned char g_occ[BATCH * R3];
__device__ float4        g_acc[BATCH * R3];

__device__ __forceinline__ void red_add_f32x4(float4* addr, float x, float y,
                                              float z, float w) {
    asm volatile("red.global.add.v4.f32 [%0], {%1, %2, %3, %4};"
                 :: "l"(addr), "f"(x), "f"(y), "f"(z), "f"(w)
                 : "memory");
}

// ---------------------------------------------------------------------------
// init: occ = 0, acc = (0,0,0,EPS_W). d_out is fully written by finalize.
// One thread handles 4 voxels.
// ---------------------------------------------------------------------------
__global__ void init_kernel() {
    int i = blockIdx.x * blockDim.x + threadIdx.x;   // 4-voxel group index
    if (i >= BATCH * R3 / 4) return;
    ((unsigned int*)g_occ)[i] = 0u;
    float4 z = make_float4(0.0f, 0.0f, 0.0f, EPS_W);
    float4* a = g_acc + (size_t)i * 4;
    a[0] = z; a[1] = z; a[2] = z; a[3] = z;
}

// ---------------------------------------------------------------------------
// tet occupancy: one block per (b, tet); 125 lanes cover the 5^3 window.
// ---------------------------------------------------------------------------
__global__ void tet_kernel(const float* __restrict__ verts,
                           const int*   __restrict__ tets) {
    int blk = blockIdx.x;           // b * NT + t
    int b = blk / NT_TOT;
    int t = blk - b * NT_TOT;
    int j = threadIdx.x;
    if (j >= 125) return;

    const int* ti = tets + (size_t)t * 4;
    const float* vb = verts + (size_t)b * NV_TOT * 3;

    const float* p0 = vb + (size_t)ti[0] * 3;
    const float* p1 = vb + (size_t)ti[1] * 3;
    const float* p2 = vb + (size_t)ti[2] * 3;
    const float* p3 = vb + (size_t)ti[3] * 3;

    float ax = p0[0], ay = p0[1], az = p0[2];
    float bxv = p1[0], byv = p1[1], bzv = p1[2];
    float cxv = p2[0], cyv = p2[1], czv = p2[2];
    float dxv = p3[0], dyv = p3[1], dzv = p3[2];

    float e1x = bxv - ax, e1y = byv - ay, e1z = bzv - az;
    float e2x = cxv - ax, e2y = cyv - ay, e2z = czv - az;
    float e3x = dxv - ax, e3y = dyv - ay, e3z = dzv - az;

    float c23x = e2y * e3z - e2z * e3y;
    float c23y = e2z * e3x - e2x * e3z;
    float c23z = e2x * e3y - e2y * e3x;

    float vol6 = e1x * c23x + e1y * c23y + e1z * c23z;
    bool volok = fabsf(vol6) > 1e-12f;
    float iv = volok ? (1.0f / vol6) : 1.0f;

    int anx  = (int)floorf(fminf(fminf(ax, bxv), fminf(cxv, dxv)) * (float)R);
    int any_ = (int)floorf(fminf(fminf(ay, byv), fminf(cyv, dyv)) * (float)R);
    int anz  = (int)floorf(fminf(fminf(az, bzv), fminf(czv, dzv)) * (float)R);

    int t0 = anx + j / 25;
    int t1 = any_ + (j / 5) % 5;
    int t2 = anz + j % 5;

    if (t0 < 0 || t0 >= R || t1 < 0 || t1 >= R || t2 < 0 || t2 >= R) return;
    if (!volok) return;

    float px = ((float)t0 + 0.5f) * (1.0f / (float)R) - ax;
    float py = ((float)t1 + 0.5f) * (1.0f / (float)R) - ay;
    float pz = ((float)t2 + 0.5f) * (1.0f / (float)R) - az;

    float l1 = (px * c23x + py * c23y + pz * c23z) * iv;

    float q1x = py * e3z - pz * e3y;
    float q1y = pz * e3x - px * e3z;
    float q1z = px * e3y - py * e3x;
    float l2 = (q1x * e1x + q1y * e1y + q1z * e1z) * iv;

    float q2x = e2y * pz - e2z * py;
    float q2y = e2z * px - e2x * pz;
    float q2z = e2x * py - e2y * px;
    float l3 = (q2x * e1x + q2y * e1y + q2z * e1z) * iv;

    if (l1 >= 0.0f && l2 >= 0.0f && l3 >= 0.0f && (l1 + l2 + l3) <= 1.0f) {
        g_occ[b * R3 + (t2 * R + t1) * R + t0] = 1;
    }
}

// ---------------------------------------------------------------------------
// surface splat: one block per (b, surf vertex); 343 lanes cover 7^3 window.
// Single float4 vector reduction per voxel: (w*c0, w*c1, w*c2, w).
// ---------------------------------------------------------------------------
__global__ void splat_kernel(const float* __restrict__ verts,
                             const float* __restrict__ code) {
    int blk = blockIdx.x;           // b * NSURF + v
    int b = blk / NSURF_N;
    int v = blk - b * NSURF_N;
    int j = threadIdx.x;
    if (j >= 343) return;

    const float* vp = verts + ((size_t)b * NV_TOT + v) * 3;
    float vx = vp[0], vy = vp[1], vz = vp[2];
    const float* cp = code + ((size_t)b * NSURF_N + v) * 3;
    float c0 = cp[0], c1 = cp[1], c2 = cp[2];

    int bx = (int)floorf(vx * (float)R);
    int by = (int)floorf(vy * (float)R);
    int bz = (int)floorf(vz * (float)R);

    int s0 = bx + j / 49 - 3;
    int s1 = by + (j / 7) % 7 - 3;
    int s2 = bz + j % 7 - 3;
    if (s0 < 0 || s0 >= R || s1 < 0 || s1 >= R || s2 < 0 || s2 >= R) return;

    float dx = ((float)s0 + 0.5f) * (1.0f / (float)R) - vx;
    float dy = ((float)s1 + 0.5f) * (1.0f / (float)R) - vy;
    float dz = ((float)s2 + 0.5f) * (1.0f / (float)R) - vz;
    float d2 = dx * dx + dy * dy + dz * dz;
    float w = __expf(-d2 * INV2SIG2);

    int vox = (s2 * R + s1) * R + s0;
    red_add_f32x4(&g_acc[b * R3 + vox], w * c0, w * c1, w * c2, w);
}

// ---------------------------------------------------------------------------
// finalize: out[b,c,vox] = acc.c / acc.w * occ. 4 voxels per thread,
// float4 loads from acc, uchar4 occ, float4 stores per channel plane.
// ---------------------------------------------------------------------------
__global__ void finalize_kernel(float* __restrict__ out) {
    int i = blockIdx.x * blockDim.x + threadIdx.x;   // 4-voxel group
    if (i >= BATCH * R3 / 4) return;
    int gi  = i * 4;             // first voxel (global, incl. batch)
    int b   = gi >> 21;          // / R3
    int vox = gi & (R3 - 1);

    uchar4 oc = ((const uchar4*)g_occ)[i];
    const float4* a = g_acc + gi;
    float4 a0 = a[0], a1 = a[1], a2 = a[2], a3 = a[3];

    float s0 = (float)oc.x / a0.w;
    float s1 = (float)oc.y / a1.w;
    float s2 = (float)oc.z / a2.w;
    float s3 = (float)oc.w / a3.w;

    float* ob = out + (size_t)b * 3 * R3 + vox;
    *(float4*)(ob)          = make_float4(a0.x * s0, a1.x * s1, a2.x * s2, a3.x * s3);
    *(float4*)(ob + R3)     = make_float4(a0.y * s0, a1.y * s1, a2.y * s2, a3.y * s3);
    *(float4*)(ob + 2 * R3) = make_float4(a0.z * s0, a1.z * s1, a2.z * s2, a3.z * s3);
}

// ---------------------------------------------------------------------------
extern "C" void kernel_launch(void* const* d_in, const int* in_sizes, int n_in,
                              void* d_out, int out_size) {
    const float* smpl_vertices = (const float*)d_in[0]; // (2, 7700, 3)
    const float* vertex_code   = (const float*)d_in[1]; // (2, 6890, 3)
    // d_in[2] = face_indices — dead code in the reference, unused.
    const int*   tet_indices   = (const int*)d_in[3];   // (30000, 4)
    float* out = (float*)d_out;                         // (2, 3, 128, 128, 128)

    {
        int n = BATCH * R3 / 4;
        init_kernel<<<(n + 255) / 256, 256>>>();
    }
    tet_kernel<<<BATCH * NT_TOT, 128>>>(smpl_vertices, tet_indices);
    splat_kernel<<<BATCH * NSURF_N, 352>>>(smpl_vertices, vertex_code);
    {
        int n = BATCH * R3 / 4;
        finalize_kernel<<<(n + 255) / 256, 256>>>(out);
    }
}